// round 12
// baseline (speedup 1.0000x reference)
#include <cuda_runtime.h>
#include <cuda_fp16.h>

#define NMAX 100000
#define HD 32
#define CAP 80

typedef unsigned long long ull;

// ---------------- scratch (static __device__, no allocation) ----------------
__device__ __align__(16) __half d_Th[NMAX * HD];  // fp16 per-node transform [V,h]@W_top
__device__ __align__(16) float  d_h[NMAX * HD];   // h = relu(agg) per node
__device__ float2 d_V[NMAX];                      // running V
__device__ __align__(16) uint4  d_E[(long)NMAX * CAP]; // {soff(=s*64), h2(m,m), h2(ef01), h2(ef23)}
__device__ int    d_cursor[NMAX];                 // per-receiver count (atomic)
__device__ __align__(16) float4 d_S4[NMAX];       // sum(mask*ef) per receiver
__device__ float  d_Smask[NMAX];                  // sum(mask) per receiver
__device__ float  d_pool[HD];                     // atomic pooled sum of h
__device__ float  d_g[HD];                        // global supernode state
__device__ float  d_c[HD];                        // g@W_n_bot + b_n (per layer)
__device__ float  d_A2[2 * HD];                   // init affine map rows
__device__ float  d_c0[HD];                       // init affine bias

__device__ __forceinline__ unsigned packh2(float a, float b) {
    __half2 h = __floats2half2_rn(a, b);
    return *reinterpret_cast<unsigned*>(&h);
}
__device__ __forceinline__ __half2 u2h(unsigned u) {
    return *reinterpret_cast<__half2*>(&u);
}
__device__ __forceinline__ ull bcast64(float a) {        // {a,a} packed
    ull r; asm("mov.b64 %0, {%1, %1};" : "=l"(r) : "f"(a)); return r;
}
__device__ __forceinline__ void fma2(ull& acc, ull a, ull b) {
    asm("fma.rn.f32x2 %0, %1, %2, %0;" : "+l"(acc) : "l"(a), "l"(b));
}
__device__ __forceinline__ float2 unpack64(ull v) {
    float2 f; asm("mov.b64 {%0, %1}, %2;" : "=f"(f.x), "=f"(f.y) : "l"(v)); return f;
}
__device__ __forceinline__ void cp16(unsigned saddr, const void* g) {
    asm volatile("cp.async.cg.shared.global [%0], [%1], 16;" :: "r"(saddr), "l"(g));
}
#define CP_COMMIT() asm volatile("cp.async.commit_group;" ::: "memory")
#define CP_WAIT(n)  asm volatile("cp.async.wait_group %0;" :: "n"(n) : "memory")

// ---------------- zero + init-affine prep ----------------
__global__ void k_zero(const float* __restrict__ W_in, const float* __restrict__ b_in,
                       const float* __restrict__ W_msg, int N) {
    int i = blockIdx.x * blockDim.x + threadIdx.x;
    if (i < N) d_cursor[i] = 0;
    if (blockIdx.x == 0 && threadIdx.x < HD) {
        int j = threadIdx.x;
        d_g[j] = 0.f; d_pool[j] = 0.f;
        const float* Wt = W_msg;       // layer 0 top rows (34 x 32)
        float c0 = Wt[j];              // V0=(1,0) -> + Wt[0][j]
        float a0 = 0.f, a1 = 0.f;
        for (int k = 0; k < HD; k++) {
            float wt = Wt[(2 + k) * HD + j];
            c0 += b_in[k] * wt;
            a0 += W_in[k] * wt;
            a1 += W_in[HD + k] * wt;
        }
        d_A2[j] = a0; d_A2[HD + j] = a1; d_c0[j] = c0;
    }
}

// ---------------- bucket fill: 1 atomic + one 16B store per edge ----------------
__device__ __forceinline__ void fill_one(int s, int r, float m, float4 f) {
    int pos = atomicAdd(&d_cursor[r], 1);
    if (pos < CAP) {
        uint4 ent;
        ent.x = ((unsigned)s) << 6;        // byte offset of fp16 T row (32*2B)
        ent.y = packh2(m, m);              // broadcast mask as half2
        ent.z = packh2(f.x, f.y);
        ent.w = packh2(f.z, f.w);
        d_E[(long)r * CAP + pos] = ent;
    }
}

__global__ void k_fill(const int* __restrict__ send, const int* __restrict__ recv,
                       const float* __restrict__ mask, const float4* __restrict__ ef,
                       int E) {
    int base = (blockIdx.x * blockDim.x + threadIdx.x) * 8;
    if (base + 8 <= E) {
        #pragma unroll
        for (int q = 0; q < 2; q++) {
            int b = base + q * 4;
            int4 s = *(const int4*)(send + b);
            int4 r = *(const int4*)(recv + b);
            float4 m = *(const float4*)(mask + b);
            float4 f0 = ef[b], f1 = ef[b + 1], f2 = ef[b + 2], f3 = ef[b + 3];
            fill_one(s.x, r.x, m.x, f0);
            fill_one(s.y, r.y, m.y, f1);
            fill_one(s.z, r.z, m.z, f2);
            fill_one(s.w, r.w, m.w, f3);
        }
    } else {
        for (int e = base; e < E; e++)
            fill_one(send[e], recv[e], mask[e], ef[e]);
    }
}

// init: T0 = pq.x*A0 + pq.y*A1 + c0 (affine), V0=(1,0). Thread per (node, dim pair).
__global__ void k_init(const float2* __restrict__ PQ, int N) {
    __shared__ float sA0[HD], sA1[HD], sc0[HD];
    if (threadIdx.x < HD) {
        sA0[threadIdx.x] = d_A2[threadIdx.x];
        sA1[threadIdx.x] = d_A2[HD + threadIdx.x];
        sc0[threadIdx.x] = d_c0[threadIdx.x];
    }
    __syncthreads();
    int gid = blockIdx.x * blockDim.x + threadIdx.x;
    int node = gid >> 4, sub = gid & 15;
    if (node >= N) return;
    float2 pq = PQ[node];
    int d0 = 2 * sub;
    float t0 = pq.x * sA0[d0] + pq.y * sA1[d0] + sc0[d0];
    float t1 = pq.x * sA0[d0 + 1] + pq.y * sA1[d0 + 1] + sc0[d0 + 1];
    *(__half2*)&d_Th[node * HD + d0] = __floats2half2_rn(t0, t1);
    if (sub == 0) d_V[node] = make_float2(1.f, 0.f);
}

// aggregation: cp.async double-buffered entry staging; gathers decoupled via LDS.
// Writes h (post-relu); u-GEMV moved to k_node. FIRST computes S4/Smask inline.
template<bool FIRST>
__global__ void __launch_bounds__(256) k_aggT(
        const float* __restrict__ W_msg, const float* __restrict__ b_msg,
        int l, int N) {
    __shared__ float sWb[4 * HD], sb[HD];
    __shared__ float sh_h[8][HD];
    __shared__ __align__(16) uint4 s_ent[8][2][32];   // [warp][buf][entry]
    const float* Wl = W_msg + l * 38 * HD;
    for (int i = threadIdx.x; i < 4 * HD; i += blockDim.x) sWb[i] = Wl[34 * HD + i];
    for (int i = threadIdx.x; i < HD; i += blockDim.x) sb[i] = b_msg[l * HD + i];
    __syncthreads();
    int w = threadIdx.x >> 5;
    int lane = threadIdx.x & 31;
    int half = lane >> 4, sub = lane & 15;
    int d0 = 2 * sub;
    int r = blockIdx.x * 8 + w;
    bool valid = r < N;
    float a0 = 0.f, a1 = 0.f, b0 = 0.f, b1 = 0.f;
    float sx = 0.f, sy = 0.f, sz = 0.f, sw = 0.f, sm = 0.f;
    if (valid) {
        const uint4* Eb = d_E + (long)r * CAP;
        const char* Tb = (const char*)d_Th;
        int subOff = sub * 4;
        int cnt = min(d_cursor[r], CAP);
        if (cnt > 0) {
            // prefetch chunk 0
            if (lane < min(32, cnt))
                cp16((unsigned)__cvta_generic_to_shared(&s_ent[w][0][lane]), Eb + lane);
            CP_COMMIT();
            int buf = 0;
            for (int base = 0; base < cnt; base += 32, buf ^= 1) {
                int c = min(32, cnt - base);
                __syncwarp();                       // prior buf^1 readers done
                int nbase = base + 32;
                if (nbase < cnt) {
                    if (lane < min(32, cnt - nbase))
                        cp16((unsigned)__cvta_generic_to_shared(&s_ent[w][buf ^ 1][lane]),
                             Eb + nbase + lane);
                    CP_COMMIT();
                    CP_WAIT(1);                     // current buf arrived
                } else {
                    CP_WAIT(0);
                }
                __syncwarp();
                if (FIRST && lane < c) {            // S4 side-sums, one entry per lane
                    uint4 q = s_ent[w][buf][lane];
                    __half2 m = u2h(q.y);
                    float2 f01 = __half22float2(__hmul2(m, u2h(q.z)));
                    float2 f23 = __half22float2(__hmul2(m, u2h(q.w)));
                    sx += f01.x; sy += f01.y;
                    sz += f23.x; sw += f23.y;
                    sm += __low2float(m);
                }
                // gather loop: entry j lo-8B at Eh[2j]; pair i: edge 2i+half
                const uint2* Eh = (const uint2*)&s_ent[w][buf][0];
                int npair = c >> 1;
                int i = 0;
                for (; i + 2 <= npair; i += 2) {
                    uint2 e0 = Eh[4 * i + 2 * half];
                    uint2 e1 = Eh[4 * i + 4 + 2 * half];
                    __half2 t0 = *(const __half2*)(Tb + e0.x + subOff);
                    __half2 t1 = *(const __half2*)(Tb + e1.x + subOff);
                    __half2 acc = __hfma2(u2h(e1.y), t1, __hmul2(u2h(e0.y), t0));
                    float2 f = __half22float2(acc);
                    a0 += f.x; a1 += f.y;
                }
                if (i < npair) {
                    uint2 e = Eh[4 * i + 2 * half];
                    __half2 t0 = *(const __half2*)(Tb + e.x + subOff);
                    float2 f = __half22float2(__hmul2(u2h(e.y), t0));
                    b0 += f.x; b1 += f.y;
                }
                if (c & 1) {                        // odd tail edge c-1: half0 only
                    uint2 e = Eh[2 * (c - 1)];
                    if (!half) {
                        __half2 t0 = *(const __half2*)(Tb + e.x + subOff);
                        float2 f = __half22float2(__hmul2(u2h(e.y), t0));
                        b0 += f.x; b1 += f.y;
                    }
                }
            }
        }
        if (FIRST) {
            #pragma unroll
            for (int o = 16; o; o >>= 1) {
                sx += __shfl_xor_sync(~0u, sx, o);
                sy += __shfl_xor_sync(~0u, sy, o);
                sz += __shfl_xor_sync(~0u, sz, o);
                sw += __shfl_xor_sync(~0u, sw, o);
                sm += __shfl_xor_sync(~0u, sm, o);
            }
            if (lane == 0) {
                d_S4[r] = make_float4(sx, sy, sz, sw);
                d_Smask[r] = sm;
            }
        } else {
            float4 s4 = d_S4[r];
            sx = s4.x; sy = s4.y; sz = s4.z; sw = s4.w;
            sm = d_Smask[r];
        }
    }
    // epilogue: combine halves, apply message-bias term, relu, store h, pool
    float h0 = 0.f, h1 = 0.f;
    if (valid) {
        float s0 = a0 + b0, s1 = a1 + b1;
        s0 += __shfl_xor_sync(~0u, s0, 16);
        s1 += __shfl_xor_sync(~0u, s1, 16);
        int d1 = d0 + 1;
        s0 += sx * sWb[d0] + sy * sWb[HD + d0] + sz * sWb[2 * HD + d0] +
              sw * sWb[3 * HD + d0] + sm * sb[d0];
        s1 += sx * sWb[d1] + sy * sWb[HD + d1] + sz * sWb[2 * HD + d1] +
              sw * sWb[3 * HD + d1] + sm * sb[d1];
        h0 = fmaxf(s0, 0.f);
        h1 = fmaxf(s1, 0.f);
        if (lane < 16) *(float2*)&d_h[r * HD + d0] = make_float2(h0, h1);
    }
    if (lane < 16) *(float2*)&sh_h[w][d0] = valid ? make_float2(h0, h1)
                                                  : make_float2(0.f, 0.f);
    __syncthreads();
    if (w == 0) {
        float ps = 0.f;
        #pragma unroll
        for (int q = 0; q < 8; q++) ps += sh_h[q][lane];
        atomicAdd(&d_pool[lane], ps);
    }
}

// global supernode update + precompute c = g_new @ W_n[32:64] + b_n ; re-zero pool
__global__ void k_g(const float* __restrict__ W_g, const float* __restrict__ b_g,
                    const float* __restrict__ W_n, const float* __restrict__ b_n,
                    int l, int N) {
    int j = threadIdx.x;  // 32 threads
    float p = d_pool[j] / (float)N;
    d_pool[j] = 0.f;
    float gold = d_g[j];
    const float* Wg = W_g + l * 64 * HD;
    float acc = b_g[l * HD + j];
    #pragma unroll
    for (int k = 0; k < HD; k++) {
        acc += __shfl_sync(~0u, gold, k) * Wg[k * HD + j];
        acc += __shfl_sync(~0u, p, k) * Wg[(HD + k) * HD + j];
    }
    float gn = fmaxf(acc, 0.f);
    d_g[j] = gn;
    const float* Wn = W_n + l * 64 * HD;
    float c = b_n[l * HD + j];
    #pragma unroll
    for (int k = 0; k < HD; k++)
        c += __shfl_sync(~0u, gn, k) * Wn[(HD + k) * HD + j];
    d_c[j] = c;
}

// node update: u = h@Wn_top; hn = relu(u + c); V += hn@W_out + b_out;
// T_next = [V,hn]@W_top(l+1)
__global__ void k_node(const float* __restrict__ W_n,
                       const float* __restrict__ W_out, const float* __restrict__ b_out,
                       const float* __restrict__ W_msg,
                       int l, int N, int last, float2* __restrict__ outV) {
    __shared__ float sWn[HD * HD], sWo[HD * 2], sWt[34 * HD], sc[HD];
    const float* Wn = W_n + l * 64 * HD;
    for (int i = threadIdx.x; i < HD * HD; i += blockDim.x) sWn[i] = Wn[i];
    for (int i = threadIdx.x; i < HD * 2; i += blockDim.x) sWo[i] = W_out[l * HD * 2 + i];
    if (!last) {
        const float* Wt = W_msg + (l + 1) * 38 * HD;
        for (int i = threadIdx.x; i < 34 * HD; i += blockDim.x) sWt[i] = Wt[i];
    }
    for (int i = threadIdx.x; i < HD; i += blockDim.x) sc[i] = d_c[i];
    __syncthreads();
    int r = (blockIdx.x * blockDim.x + threadIdx.x) >> 5;
    int lane = threadIdx.x & 31;
    if (r >= N) return;
    int half = lane >> 4, sub = lane & 15;
    int d0 = 2 * sub, d1 = d0 + 1;
    int kb = half * 16;
    float h = d_h[r * HD + lane];
    // u-GEMV: half-split packed
    ull uacc = 0;
    #pragma unroll
    for (int kk = 0; kk < 16; kk++) {
        float hk = __shfl_sync(~0u, h, kb + kk);
        ull wv = *(const ull*)&sWn[(kb + kk) * HD + d0];
        fma2(uacc, wv, bcast64(hk));
    }
    float2 u = unpack64(uacc);
    u.x += __shfl_xor_sync(~0u, u.x, 16);
    u.y += __shfl_xor_sync(~0u, u.y, 16);
    // redistribute pair layout -> lane=dim layout
    float ux = __shfl_sync(~0u, u.x, lane >> 1);
    float uy = __shfl_sync(~0u, u.y, lane >> 1);
    float hn = fmaxf(((lane & 1) ? uy : ux) + sc[lane], 0.f);
    float v0 = hn * sWo[lane * 2 + 0];
    float v1 = hn * sWo[lane * 2 + 1];
    #pragma unroll
    for (int o = 16; o; o >>= 1) {
        v0 += __shfl_xor_sync(~0u, v0, o);
        v1 += __shfl_xor_sync(~0u, v1, o);
    }
    float2 v = d_V[r];
    v.x += v0 + b_out[l * 2 + 0];
    v.y += v1 + b_out[l * 2 + 1];
    if (last) {
        if (lane == 0) outV[r] = v;
    } else {
        if (lane == 0) d_V[r] = v;
        ull tacc = 0;
        #pragma unroll
        for (int kk = 0; kk < 16; kk++) {
            float hk = __shfl_sync(~0u, hn, kb + kk);
            ull wv = *(const ull*)&sWt[(2 + kb + kk) * HD + d0];
            fma2(tacc, wv, bcast64(hk));
        }
        float2 t = unpack64(tacc);
        t.x += __shfl_xor_sync(~0u, t.x, 16);
        t.y += __shfl_xor_sync(~0u, t.y, 16);
        t.x += v.x * sWt[d0] + v.y * sWt[HD + d0];
        t.y += v.x * sWt[d1] + v.y * sWt[HD + d1];
        if (lane < 16)
            *(__half2*)&d_Th[r * HD + d0] = __floats2half2_rn(t.x, t.y);
    }
}

// ---------------- launch ----------------
extern "C" void kernel_launch(void* const* d_in, const int* in_sizes, int n_in,
                              void* d_out, int out_size) {
    const float2* PQ    = (const float2*)d_in[0];
    const int*    send  = (const int*)d_in[1];
    const int*    recv  = (const int*)d_in[2];
    const float4* ef    = (const float4*)d_in[3];
    const float*  mask  = (const float*)d_in[4];
    const float*  W_in  = (const float*)d_in[5];
    const float*  b_in  = (const float*)d_in[6];
    const float*  W_msg = (const float*)d_in[7];
    const float*  b_msg = (const float*)d_in[8];
    const float*  W_g   = (const float*)d_in[9];
    const float*  b_g   = (const float*)d_in[10];
    const float*  W_n   = (const float*)d_in[11];
    const float*  b_n   = (const float*)d_in[12];
    const float*  W_out = (const float*)d_in[13];
    const float*  b_out = (const float*)d_in[14];

    int N = in_sizes[0] / 2;
    int E = in_sizes[1];
    int nwb = (N + 7) / 8;          // warp-per-node kernels (256 thr)
    int eb8 = (E + 2047) / 2048;    // 8 edges/thread

    k_zero<<<(N + 255) / 256, 256>>>(W_in, b_in, W_msg, N);
    k_fill<<<eb8, 256>>>(send, recv, mask, ef, E);
    k_init<<<(N * 16 + 255) / 256, 256>>>(PQ, N);

    k_aggT<true><<<nwb, 256>>>(W_msg, b_msg, 0, N);
    k_g<<<1, 32>>>(W_g, b_g, W_n, b_n, 0, N);
    k_node<<<nwb, 256>>>(W_n, W_out, b_out, W_msg, 0, N, 0, (float2*)d_out);

    for (int l = 1; l < 3; l++) {
        k_aggT<false><<<nwb, 256>>>(W_msg, b_msg, l, N);
        k_g<<<1, 32>>>(W_g, b_g, W_n, b_n, l, N);
        k_node<<<nwb, 256>>>(W_n, W_out, b_out, W_msg, l, N, l == 2, (float2*)d_out);
    }
}

// round 13
// speedup vs baseline: 1.0639x; 1.0639x over previous
#include <cuda_runtime.h>
#include <cuda_fp16.h>

#define NMAX 100000
#define HD 32
#define CAP 80

typedef unsigned long long ull;

// ---------------- scratch (static __device__, no allocation) ----------------
__device__ __align__(16) __half d_Th[NMAX * HD];  // fp16 per-node transform [V,h]@W_top
__device__ __align__(16) float  d_u[NMAX * HD];   // h @ W_n_top (pre-relu node update)
__device__ float2 d_V[NMAX];                      // running V
__device__ __align__(16) uint4  d_E[(long)NMAX * CAP]; // {soff(=s*64), h2(m,m), h2(ef01), h2(ef23)}
__device__ int    d_cursor[NMAX];                 // per-receiver count (atomic)
__device__ __align__(16) float4 d_S4[NMAX];       // sum(mask*ef) per receiver
__device__ float  d_Smask[NMAX];                  // sum(mask) per receiver
__device__ float  d_pool[HD];                     // atomic pooled sum of h
__device__ float  d_g[HD];                        // global supernode state
__device__ float  d_c[HD];                        // g@W_n_bot + b_n (per layer)
__device__ float  d_A2[2 * HD];                   // init affine map rows
__device__ float  d_c0[HD];                       // init affine bias

__device__ __forceinline__ unsigned packh2(float a, float b) {
    __half2 h = __floats2half2_rn(a, b);
    return *reinterpret_cast<unsigned*>(&h);
}
__device__ __forceinline__ __half2 u2h(unsigned u) {
    return *reinterpret_cast<__half2*>(&u);
}
__device__ __forceinline__ ull bcast64(float a) {        // {a,a} packed
    ull r; asm("mov.b64 %0, {%1, %1};" : "=l"(r) : "f"(a)); return r;
}
__device__ __forceinline__ void fma2(ull& acc, ull a, ull b) {
    asm("fma.rn.f32x2 %0, %1, %2, %0;" : "+l"(acc) : "l"(a), "l"(b));
}
__device__ __forceinline__ float2 unpack64(ull v) {
    float2 f; asm("mov.b64 {%0, %1}, %2;" : "=f"(f.x), "=f"(f.y) : "l"(v)); return f;
}
__device__ __forceinline__ void cp16(unsigned saddr, const void* g) {
    asm volatile("cp.async.cg.shared.global [%0], [%1], 16;" :: "r"(saddr), "l"(g));
}
#define CP_COMMIT() asm volatile("cp.async.commit_group;" ::: "memory")
#define CP_WAIT(n)  asm volatile("cp.async.wait_group %0;" :: "n"(n) : "memory")

// ---------------- zero + init-affine prep ----------------
__global__ void k_zero(const float* __restrict__ W_in, const float* __restrict__ b_in,
                       const float* __restrict__ W_msg, int N) {
    int i = blockIdx.x * blockDim.x + threadIdx.x;
    if (i < N) d_cursor[i] = 0;
    if (blockIdx.x == 0 && threadIdx.x < HD) {
        int j = threadIdx.x;
        d_g[j] = 0.f; d_pool[j] = 0.f;
        const float* Wt = W_msg;       // layer 0 top rows (34 x 32)
        float c0 = Wt[j];              // V0=(1,0) -> + Wt[0][j]
        float a0 = 0.f, a1 = 0.f;
        for (int k = 0; k < HD; k++) {
            float wt = Wt[(2 + k) * HD + j];
            c0 += b_in[k] * wt;
            a0 += W_in[k] * wt;
            a1 += W_in[HD + k] * wt;
        }
        d_A2[j] = a0; d_A2[HD + j] = a1; d_c0[j] = c0;
    }
}

// ---------------- bucket fill: 1 atomic + one 16B store per edge ----------------
__device__ __forceinline__ void fill_one(int s, int r, float m, float4 f) {
    int pos = atomicAdd(&d_cursor[r], 1);
    if (pos < CAP) {
        uint4 ent;
        ent.x = ((unsigned)s) << 6;        // byte offset of fp16 T row (32*2B)
        ent.y = packh2(m, m);              // broadcast mask as half2
        ent.z = packh2(f.x, f.y);
        ent.w = packh2(f.z, f.w);
        d_E[(long)r * CAP + pos] = ent;
    }
}

__global__ void k_fill(const int* __restrict__ send, const int* __restrict__ recv,
                       const float* __restrict__ mask, const float4* __restrict__ ef,
                       int E) {
    int base = (blockIdx.x * blockDim.x + threadIdx.x) * 8;
    if (base + 8 <= E) {
        #pragma unroll
        for (int q = 0; q < 2; q++) {
            int b = base + q * 4;
            int4 s = *(const int4*)(send + b);
            int4 r = *(const int4*)(recv + b);
            float4 m = *(const float4*)(mask + b);
            float4 f0 = ef[b], f1 = ef[b + 1], f2 = ef[b + 2], f3 = ef[b + 3];
            fill_one(s.x, r.x, m.x, f0);
            fill_one(s.y, r.y, m.y, f1);
            fill_one(s.z, r.z, m.z, f2);
            fill_one(s.w, r.w, m.w, f3);
        }
    } else {
        for (int e = base; e < E; e++)
            fill_one(send[e], recv[e], mask[e], ef[e]);
    }
}

// init: T0 = pq.x*A0 + pq.y*A1 + c0 (affine), V0=(1,0). Thread per (node, dim pair).
__global__ void k_init(const float2* __restrict__ PQ, int N) {
    __shared__ float sA0[HD], sA1[HD], sc0[HD];
    if (threadIdx.x < HD) {
        sA0[threadIdx.x] = d_A2[threadIdx.x];
        sA1[threadIdx.x] = d_A2[HD + threadIdx.x];
        sc0[threadIdx.x] = d_c0[threadIdx.x];
    }
    __syncthreads();
    int gid = blockIdx.x * blockDim.x + threadIdx.x;
    int node = gid >> 4, sub = gid & 15;
    if (node >= N) return;
    float2 pq = PQ[node];
    int d0 = 2 * sub;
    float t0 = pq.x * sA0[d0] + pq.y * sA1[d0] + sc0[d0];
    float t1 = pq.x * sA0[d0 + 1] + pq.y * sA1[d0 + 1] + sc0[d0 + 1];
    *(__half2*)&d_Th[node * HD + d0] = __floats2half2_rn(t0, t1);
    if (sub == 0) d_V[node] = make_float2(1.f, 0.f);
}

// aggregation: cp.async double-buffered entry staging; gathers decoupled via LDS.
// Epilogue: combine halves + message-bias, relu, u-GEMV (smem FFMA2), pool.
template<bool FIRST>
__global__ void __launch_bounds__(256) k_aggT(
        const float* __restrict__ W_msg, const float* __restrict__ b_msg,
        const float* __restrict__ W_n, int l, int N) {
    __shared__ float sWb[4 * HD], sb[HD], sWn[HD * HD];
    __shared__ float sh_h[8][HD];
    __shared__ __align__(16) uint4 s_ent[8][2][32];   // [warp][buf][entry]
    const float* Wl = W_msg + l * 38 * HD;
    const float* Wn = W_n + l * 64 * HD;
    for (int i = threadIdx.x; i < 4 * HD; i += blockDim.x) sWb[i] = Wl[34 * HD + i];
    for (int i = threadIdx.x; i < HD; i += blockDim.x) sb[i] = b_msg[l * HD + i];
    for (int i = threadIdx.x; i < HD * HD; i += blockDim.x) sWn[i] = Wn[i];
    __syncthreads();
    int w = threadIdx.x >> 5;
    int lane = threadIdx.x & 31;
    int half = lane >> 4, sub = lane & 15;
    int d0 = 2 * sub;
    int r = blockIdx.x * 8 + w;
    bool valid = r < N;
    float a0 = 0.f, a1 = 0.f, b0 = 0.f, b1 = 0.f;
    float sx = 0.f, sy = 0.f, sz = 0.f, sw = 0.f, sm = 0.f;
    if (valid) {
        const uint4* Eb = d_E + (long)r * CAP;
        const char* Tb = (const char*)d_Th;
        int subOff = sub * 4;
        int cnt = min(d_cursor[r], CAP);
        if (cnt > 0) {
            // prefetch chunk 0
            if (lane < min(32, cnt))
                cp16((unsigned)__cvta_generic_to_shared(&s_ent[w][0][lane]), Eb + lane);
            CP_COMMIT();
            int buf = 0;
            for (int base = 0; base < cnt; base += 32, buf ^= 1) {
                int c = min(32, cnt - base);
                __syncwarp();                       // prior buf^1 readers done
                int nbase = base + 32;
                if (nbase < cnt) {
                    if (lane < min(32, cnt - nbase))
                        cp16((unsigned)__cvta_generic_to_shared(&s_ent[w][buf ^ 1][lane]),
                             Eb + nbase + lane);
                    CP_COMMIT();
                    CP_WAIT(1);                     // current buf arrived
                } else {
                    CP_WAIT(0);
                }
                __syncwarp();
                if (FIRST && lane < c) {            // S4 side-sums, one entry per lane
                    uint4 q = s_ent[w][buf][lane];
                    __half2 m = u2h(q.y);
                    float2 f01 = __half22float2(__hmul2(m, u2h(q.z)));
                    float2 f23 = __half22float2(__hmul2(m, u2h(q.w)));
                    sx += f01.x; sy += f01.y;
                    sz += f23.x; sw += f23.y;
                    sm += __low2float(m);
                }
                // gather loop: entry j lo-8B at Eh[2j]; pair i: edge 2i+half
                const uint2* Eh = (const uint2*)&s_ent[w][buf][0];
                int npair = c >> 1;
                int i = 0;
                for (; i + 2 <= npair; i += 2) {
                    uint2 e0 = Eh[4 * i + 2 * half];
                    uint2 e1 = Eh[4 * i + 4 + 2 * half];
                    __half2 t0 = *(const __half2*)(Tb + e0.x + subOff);
                    __half2 t1 = *(const __half2*)(Tb + e1.x + subOff);
                    __half2 acc = __hfma2(u2h(e1.y), t1, __hmul2(u2h(e0.y), t0));
                    float2 f = __half22float2(acc);
                    a0 += f.x; a1 += f.y;
                }
                if (i < npair) {
                    uint2 e = Eh[4 * i + 2 * half];
                    __half2 t0 = *(const __half2*)(Tb + e.x + subOff);
                    float2 f = __half22float2(__hmul2(u2h(e.y), t0));
                    b0 += f.x; b1 += f.y;
                }
                if (c & 1) {                        // odd tail edge c-1: half0 only
                    uint2 e = Eh[2 * (c - 1)];
                    if (!half) {
                        __half2 t0 = *(const __half2*)(Tb + e.x + subOff);
                        float2 f = __half22float2(__hmul2(u2h(e.y), t0));
                        b0 += f.x; b1 += f.y;
                    }
                }
            }
        }
        if (FIRST) {
            #pragma unroll
            for (int o = 16; o; o >>= 1) {
                sx += __shfl_xor_sync(~0u, sx, o);
                sy += __shfl_xor_sync(~0u, sy, o);
                sz += __shfl_xor_sync(~0u, sz, o);
                sw += __shfl_xor_sync(~0u, sw, o);
                sm += __shfl_xor_sync(~0u, sm, o);
            }
            if (lane == 0) {
                d_S4[r] = make_float4(sx, sy, sz, sw);
                d_Smask[r] = sm;
            }
        } else {
            float4 s4 = d_S4[r];
            sx = s4.x; sy = s4.y; sz = s4.z; sw = s4.w;
            sm = d_Smask[r];
        }
    }
    // epilogue: combine halves, apply message-bias term, relu, u-GEMV, pool
    float h0 = 0.f, h1 = 0.f;
    if (valid) {
        float s0 = a0 + b0, s1 = a1 + b1;
        s0 += __shfl_xor_sync(~0u, s0, 16);
        s1 += __shfl_xor_sync(~0u, s1, 16);
        int d1 = d0 + 1;
        s0 += sx * sWb[d0] + sy * sWb[HD + d0] + sz * sWb[2 * HD + d0] +
              sw * sWb[3 * HD + d0] + sm * sb[d0];
        s1 += sx * sWb[d1] + sy * sWb[HD + d1] + sz * sWb[2 * HD + d1] +
              sw * sWb[3 * HD + d1] + sm * sb[d1];
        h0 = fmaxf(s0, 0.f);
        h1 = fmaxf(s1, 0.f);
    }
    if (lane < 16) *(float2*)&sh_h[w][d0] = valid ? make_float2(h0, h1)
                                                  : make_float2(0.f, 0.f);
    __syncwarp();
    if (valid) {
        ull uacc = 0;
        int kb = half * 16;
        #pragma unroll
        for (int kk = 0; kk < 16; kk++) {
            ull hh = bcast64(sh_h[w][kb + kk]);
            ull wv = *(const ull*)&sWn[(kb + kk) * HD + d0];
            fma2(uacc, wv, hh);
        }
        float2 u = unpack64(uacc);
        u.x += __shfl_xor_sync(~0u, u.x, 16);
        u.y += __shfl_xor_sync(~0u, u.y, 16);
        if (lane < 16) *(float2*)&d_u[r * HD + d0] = u;
    }
    __syncthreads();
    if (w == 0) {
        float ps = 0.f;
        #pragma unroll
        for (int q = 0; q < 8; q++) ps += sh_h[q][lane];
        atomicAdd(&d_pool[lane], ps);
    }
}

// global supernode update + precompute c = g_new @ W_n[32:64] + b_n ; re-zero pool
__global__ void k_g(const float* __restrict__ W_g, const float* __restrict__ b_g,
                    const float* __restrict__ W_n, const float* __restrict__ b_n,
                    int l, int N) {
    int j = threadIdx.x;  // 32 threads
    float p = d_pool[j] / (float)N;
    d_pool[j] = 0.f;
    float gold = d_g[j];
    const float* Wg = W_g + l * 64 * HD;
    float acc = b_g[l * HD + j];
    #pragma unroll
    for (int k = 0; k < HD; k++) {
        acc += __shfl_sync(~0u, gold, k) * Wg[k * HD + j];
        acc += __shfl_sync(~0u, p, k) * Wg[(HD + k) * HD + j];
    }
    float gn = fmaxf(acc, 0.f);
    d_g[j] = gn;
    const float* Wn = W_n + l * 64 * HD;
    float c = b_n[l * HD + j];
    #pragma unroll
    for (int k = 0; k < HD; k++)
        c += __shfl_sync(~0u, gn, k) * Wn[(HD + k) * HD + j];
    d_c[j] = c;
}

// node update: hn = relu(u + c); V += hn@W_out + b_out; T_next = [V,hn]@W_top(l+1)
__global__ void k_node(const float* __restrict__ W_out, const float* __restrict__ b_out,
                       const float* __restrict__ W_msg,
                       int l, int N, int last, float2* __restrict__ outV) {
    __shared__ float sWo[HD * 2], sWt[34 * HD], sc[HD];
    for (int i = threadIdx.x; i < HD * 2; i += blockDim.x) sWo[i] = W_out[l * HD * 2 + i];
    if (!last) {
        const float* Wt = W_msg + (l + 1) * 38 * HD;
        for (int i = threadIdx.x; i < 34 * HD; i += blockDim.x) sWt[i] = Wt[i];
    }
    for (int i = threadIdx.x; i < HD; i += blockDim.x) sc[i] = d_c[i];
    __syncthreads();
    int r = (blockIdx.x * blockDim.x + threadIdx.x) >> 5;
    int lane = threadIdx.x & 31;
    if (r >= N) return;
    float hn = fmaxf(d_u[r * HD + lane] + sc[lane], 0.f);
    float v0 = hn * sWo[lane * 2 + 0];
    float v1 = hn * sWo[lane * 2 + 1];
    #pragma unroll
    for (int o = 16; o; o >>= 1) {
        v0 += __shfl_xor_sync(~0u, v0, o);
        v1 += __shfl_xor_sync(~0u, v1, o);
    }
    float2 v = d_V[r];
    v.x += v0 + b_out[l * 2 + 0];
    v.y += v1 + b_out[l * 2 + 1];
    if (last) {
        if (lane == 0) outV[r] = v;
    } else {
        if (lane == 0) d_V[r] = v;
        int half = lane >> 4, sub = lane & 15;
        int d0 = 2 * sub, d1 = d0 + 1;
        int kb = half * 16;
        ull tacc = 0;
        #pragma unroll
        for (int kk = 0; kk < 16; kk++) {
            float hk = __shfl_sync(~0u, hn, kb + kk);
            ull wv = *(const ull*)&sWt[(2 + kb + kk) * HD + d0];
            fma2(tacc, wv, bcast64(hk));
        }
        float2 t = unpack64(tacc);
        t.x += __shfl_xor_sync(~0u, t.x, 16);
        t.y += __shfl_xor_sync(~0u, t.y, 16);
        t.x += v.x * sWt[d0] + v.y * sWt[HD + d0];
        t.y += v.x * sWt[d1] + v.y * sWt[HD + d1];
        if (lane < 16)
            *(__half2*)&d_Th[r * HD + d0] = __floats2half2_rn(t.x, t.y);
    }
}

// ---------------- launch ----------------
extern "C" void kernel_launch(void* const* d_in, const int* in_sizes, int n_in,
                              void* d_out, int out_size) {
    const float2* PQ    = (const float2*)d_in[0];
    const int*    send  = (const int*)d_in[1];
    const int*    recv  = (const int*)d_in[2];
    const float4* ef    = (const float4*)d_in[3];
    const float*  mask  = (const float*)d_in[4];
    const float*  W_in  = (const float*)d_in[5];
    const float*  b_in  = (const float*)d_in[6];
    const float*  W_msg = (const float*)d_in[7];
    const float*  b_msg = (const float*)d_in[8];
    const float*  W_g   = (const float*)d_in[9];
    const float*  b_g   = (const float*)d_in[10];
    const float*  W_n   = (const float*)d_in[11];
    const float*  b_n   = (const float*)d_in[12];
    const float*  W_out = (const float*)d_in[13];
    const float*  b_out = (const float*)d_in[14];

    int N = in_sizes[0] / 2;
    int E = in_sizes[1];
    int nwb = (N + 7) / 8;          // warp-per-node kernels (256 thr)
    int eb8 = (E + 2047) / 2048;    // 8 edges/thread

    k_zero<<<(N + 255) / 256, 256>>>(W_in, b_in, W_msg, N);
    k_fill<<<eb8, 256>>>(send, recv, mask, ef, E);
    k_init<<<(N * 16 + 255) / 256, 256>>>(PQ, N);

    k_aggT<true><<<nwb, 256>>>(W_msg, b_msg, W_n, 0, N);
    k_g<<<1, 32>>>(W_g, b_g, W_n, b_n, 0, N);
    k_node<<<nwb, 256>>>(W_out, b_out, W_msg, 0, N, 0, (float2*)d_out);

    for (int l = 1; l < 3; l++) {
        k_aggT<false><<<nwb, 256>>>(W_msg, b_msg, W_n, l, N);
        k_g<<<1, 32>>>(W_g, b_g, W_n, b_n, l, N);
        k_node<<<nwb, 256>>>(W_out, b_out, W_msg, l, N, l == 2, (float2*)d_out);
    }
}